// round 2
// baseline (speedup 1.0000x reference)
#include <cuda_runtime.h>
#include <cuda_bf16.h>

// Shapes (fixed by the problem):
//   B=2048, V=256, T=11, K=8, N=8, H=255, K*H=2040
//   x_unfolded: (B, V, T, K) fp32, exact one-hot along V
//   scanner_w : (N, V, K)
//   hidden_w  : (K*H, N)
//   out_w     : (2, K*H)
//   out_b     : (2,)
//   out       : (B, 2, T) fp32
//
// Collapse: out[b,o,t] = out_b[o] + sum_k LUT[o][k][ids[b,t,k]]
// with LUT[o][k][v] = sum_h out_w[o, k*H+h] * relu( sum_n hidden_w[k*H+h, n]
//                       * relu(scanner_w[n, v, k]) )

#define BB 2048
#define VV 256
#define TT 11
#define KK 8
#define NN 8
#define HH 255
#define KH 2040

// (2, K, V) lookup table, 16 KB
__device__ float d_LUT[2 * KK * VV];

// ---------------------------------------------------------------------------
// Kernel 1: build the LUT. One warp per (k, v) pair -> 2048 warps.
// ---------------------------------------------------------------------------
__global__ void lut_kernel(const float* __restrict__ sw,   // (N, V, K)
                           const float* __restrict__ hw,   // (K*H, N)
                           const float* __restrict__ ow)   // (2, K*H)
{
    int w    = (blockIdx.x * blockDim.x + threadIdx.x) >> 5;  // global warp id
    int lane = threadIdx.x & 31;
    if (w >= KK * VV) return;
    int k = w >> 8;        // 0..7
    int v = w & 255;       // 0..255

    // s[n] = relu(scanner_w[n, v, k]) — broadcast load, all lanes same addr
    float s[NN];
#pragma unroll
    for (int n = 0; n < NN; n++)
        s[n] = fmaxf(sw[n * (VV * KK) + v * KK + k], 0.0f);

    float a0 = 0.0f, a1 = 0.0f;
    for (int h = lane; h < HH; h += 32) {
        int c = k * HH + h;
        const float4* hr = (const float4*)(hw + c * NN);  // 32B-aligned
        float4 h0 = hr[0], h1 = hr[1];
        float acc = h0.x * s[0] + h0.y * s[1] + h0.z * s[2] + h0.w * s[3]
                  + h1.x * s[4] + h1.y * s[5] + h1.z * s[6] + h1.w * s[7];
        acc = fmaxf(acc, 0.0f);
        a0 += ow[c] * acc;
        a1 += ow[KH + c] * acc;
    }
#pragma unroll
    for (int off = 16; off; off >>= 1) {
        a0 += __shfl_xor_sync(0xffffffffu, a0, off);
        a1 += __shfl_xor_sync(0xffffffffu, a1, off);
    }
    if (lane == 0) {
        d_LUT[k * VV + v]           = a0;
        d_LUT[KK * VV + k * VV + v] = a1;
    }
}

// ---------------------------------------------------------------------------
// Kernel 2: stream x_unfolded (184.5 MB), one block per batch row b.
// Per-b slab = V*T*K = 22528 floats = 5632 float4 = 88 KB, fully coalesced.
// Nonzeros are rare (176 of 22528 per b): rare-branch scatter into smem.
// ---------------------------------------------------------------------------
__global__ __launch_bounds__(256) void scan_kernel(
    const float4* __restrict__ x,     // (B, V, T, K) as float4
    const float*  __restrict__ out_b, // (2,)
    float*        __restrict__ out)   // (B, 2, T)
{
    __shared__ float acc[2][TT];
    int tid = threadIdx.x;
    if (tid < 2 * TT) acc[tid / TT][tid % TT] = 0.0f;
    __syncthreads();

    const float4* xb = x + (size_t)blockIdx.x * (VV * TT * KK / 4);  // 5632

#pragma unroll
    for (int j = 0; j < 22; j++) {
        int i4 = tid + j * 256;
        float4 q = xb[i4];
        if (q.x != 0.0f || q.y != 0.0f || q.z != 0.0f || q.w != 0.0f) {
            int r  = i4 * 4;            // offset within slab
            int v  = r / (TT * KK);     // r / 88
            int rr = r - v * (TT * KK);
            int t  = rr >> 3;           // same t for whole float4 (88 % 4 == 0)
            int k0 = rr & 7;            // 0 or 4
            float vals[4] = {q.x, q.y, q.z, q.w};
#pragma unroll
            for (int qq = 0; qq < 4; qq++) {
                if (vals[qq] != 0.0f) {
                    int k = k0 + qq;
                    atomicAdd(&acc[0][t], vals[qq] * d_LUT[k * VV + v]);
                    atomicAdd(&acc[1][t], vals[qq] * d_LUT[KK * VV + k * VV + v]);
                }
            }
        }
    }
    __syncthreads();

    if (tid < 2 * TT) {
        int o = tid / TT, t = tid % TT;
        out[((size_t)blockIdx.x * 2 + o) * TT + t] = acc[o][t] + out_b[o];
    }
}

// ---------------------------------------------------------------------------
extern "C" void kernel_launch(void* const* d_in, const int* in_sizes, int n_in,
                              void* d_out, int out_size)
{
    const float* x   = (const float*)d_in[0];  // (B, V, T, K)
    const float* sw  = (const float*)d_in[1];  // (N, V, K)
    const float* hw  = (const float*)d_in[2];  // (K*H, N)
    const float* ow  = (const float*)d_in[3];  // (2, K*H)
    const float* ob  = (const float*)d_in[4];  // (2,)
    float* out = (float*)d_out;                // (B, 2, T)

    (void)in_sizes; (void)n_in; (void)out_size;

    // 2048 warps for the LUT -> 256 blocks x 256 threads (8 warps each)
    lut_kernel<<<256, 256>>>(sw, hw, ow);
    // one block per batch row
    scan_kernel<<<BB, 256>>>((const float4*)x, ob, out);
}